// round 12
// baseline (speedup 1.0000x reference)
#include <cuda_runtime.h>
#include <math.h>

#define NB 64
#define NQ 128
#define ND 512
#define NP 129
#define EPS_ 1e-8f
#define FULLM 0xffffffffu

// scratch (device globals; no allocation allowed)
__device__ float g_rn[NB * NQ * ND];
__device__ float g_en[NB * NQ * ND];
__device__ float g_cost[NB * NQ * NQ];

// order-preserving float <-> uint encoding (min uint == min float, exact)
__device__ __forceinline__ unsigned ford(float f) {
    unsigned u = __float_as_uint(f);
    return (u & 0x80000000u) ? ~u : (u | 0x80000000u);
}
__device__ __forceinline__ float funord(unsigned u) {
    return __uint_as_float((u & 0x80000000u) ? (u ^ 0x80000000u) : ~u);
}

#define FMA2(d, a, b) \
    asm("fma.rn.f32x2 %0, %1, %2, %3;" : "=l"(d) : "l"(a), "l"(b), "l"(d))
#define PACK2(d, x) \
    asm("mov.b64 %0, {%1, %1};" : "=l"(d) : "r"(__float_as_uint(x)))

// ---------------------------------------------------------------------------
// Kernel 1: row-wise normalize; also zeroes the loss accumulator.
// ---------------------------------------------------------------------------
__global__ void normalize_kernel(const float* __restrict__ r,
                                 const float* __restrict__ e,
                                 float* __restrict__ out) {
    if (blockIdx.x == 0 && threadIdx.x == 0) out[0] = 0.f;
    int gw = (blockIdx.x * blockDim.x + threadIdx.x) >> 5;
    int lane = threadIdx.x & 31;
    if (gw >= 2 * NB * NQ) return;
    const float* src;
    float* dst;
    if (gw < NB * NQ) { src = r + (size_t)gw * ND;            dst = g_rn + (size_t)gw * ND; }
    else              { src = e + (size_t)(gw - NB*NQ) * ND;  dst = g_en + (size_t)(gw - NB*NQ) * ND; }

    float vals[16];
    float ss = 0.f;
#pragma unroll
    for (int k = 0; k < 16; k++) {
        float x = src[lane + 32 * k] + EPS_;
        vals[k] = x;
        ss += x * x;
    }
#pragma unroll
    for (int o = 16; o > 0; o >>= 1)
        ss += __shfl_xor_sync(FULLM, ss, o);
    float n = sqrtf(ss);
    float s = 1.f / fmaxf(n, EPS_);
#pragma unroll
    for (int k = 0; k < 16; k++)
        dst[lane + 32 * k] = vals[k] * s;
}

// ---------------------------------------------------------------------------
// Kernel 2: batched cost GEMM with packed f32x2 FMA (R11-proven).
// ---------------------------------------------------------------------------
__global__ void cost_kernel() {
    __shared__ float sr[64][33];
    __shared__ __align__(16) float se2[32][130];   // [kk][col], 64 cols + pad
    int b  = blockIdx.z;
    int ti = blockIdx.y;
    int tj = blockIdx.x;
    const float* rb = g_rn + (size_t)b * NQ * ND + (size_t)ti * 64 * ND;
    const float* eb = g_en + (size_t)b * NQ * ND + (size_t)tj * 64 * ND;
    int tx = threadIdx.x, ty = threadIdx.y;
    int tid = ty * 16 + tx;

    unsigned long long acc[4][2];
#pragma unroll
    for (int u = 0; u < 4; u++) { acc[u][0] = 0ULL; acc[u][1] = 0ULL; }

    for (int k0 = 0; k0 < ND; k0 += 32) {
        for (int t = tid; t < 64 * 32; t += 256) {
            int row = t >> 5, kk = t & 31;
            sr[row][kk]  = rb[(size_t)row * ND + k0 + kk];
            se2[kk][row] = eb[(size_t)row * ND + k0 + kk];
        }
        __syncthreads();
#pragma unroll 8
        for (int kk = 0; kk < 32; kk++) {
            unsigned long long b01 = *(const unsigned long long*)&se2[kk][tx * 4];
            unsigned long long b23 = *(const unsigned long long*)&se2[kk][tx * 4 + 2];
#pragma unroll
            for (int u = 0; u < 4; u++) {
                unsigned long long a2;
                PACK2(a2, sr[ty * 4 + u][kk]);
                FMA2(acc[u][0], a2, b01);
                FMA2(acc[u][1], a2, b23);
            }
        }
        __syncthreads();
    }

    float* cb = g_cost + (size_t)b * NQ * NQ;
#pragma unroll
    for (int u = 0; u < 4; u++) {
        int i = ti * 64 + ty * 4 + u;
        float4 w;
        w.x = -__uint_as_float((unsigned)(acc[u][0]));
        w.y = -__uint_as_float((unsigned)(acc[u][0] >> 32));
        w.z = -__uint_as_float((unsigned)(acc[u][1]));
        w.w = -__uint_as_float((unsigned)(acc[u][1] >> 32));
        *(float4*)&cb[i * NQ + tj * 64 + tx * 4] = w;
    }
}

// ---------------------------------------------------------------------------
// Kernel 3: full JV (lapjv) LSA, one CTA per batch, warp 0 solves.
// Phase D: v in registers, conditional j2-REDUX, single syncwarp/iter.
// Phase F: R7/R11-proven packed (j<<8)|p key REDUX.
// ---------------------------------------------------------------------------
__global__ void lsa_kernel(float* __restrict__ out) {
    extern __shared__ float costS[];      // NQ*NQ floats
    __shared__ float vS[NQ];
    __shared__ float uS[NP];              // u indexed by row+1
    __shared__ int   pS[NP];              // col (1..NQ) -> row+1 ; 0 = free
    __shared__ int   wayS[NQ];
    __shared__ int   colsolS[NQ];
    __shared__ int   rowsolS[NQ];
    __shared__ int   cntS[NQ];
    __shared__ int   pickS[NQ];
    __shared__ int   freeS[NQ];

    int b   = blockIdx.x;
    int tid = threadIdx.x;

    const float4* cb = (const float4*)(g_cost + (size_t)b * NQ * NQ);
    float4* cs4 = (float4*)costS;
    for (int t = tid; t < NQ * NQ / 4; t += blockDim.x) cs4[t] = cb[t];
    if (tid < NQ) { cntS[tid] = 0; pickS[tid] = 0x7fffffff; }
    if (tid < NP) { uS[tid] = 0.f; pS[tid] = 0; }
    __syncthreads();
    if (tid >= 32) return;   // warp 0 only
    int lane = tid;

    // ================= Phase A: column reduction =================
    float vloc[4]; int ir[4];
#pragma unroll
    for (int k = 0; k < 4; k++) { vloc[k] = 3e38f; ir[k] = 0; }
    for (int i = 0; i < NQ; i++) {
#pragma unroll
        for (int k = 0; k < 4; k++) {
            float c = costS[i * NQ + lane + 32 * k];
            if (c < vloc[k]) { vloc[k] = c; ir[k] = i; }
        }
    }
#pragma unroll
    for (int k = 0; k < 4; k++) {
        vS[lane + 32 * k] = vloc[k];
        atomicMin(&pickS[ir[k]], lane + 32 * k);
        atomicAdd(&cntS[ir[k]], 1);
    }
    __syncwarp();
#pragma unroll
    for (int k = 0; k < 4; k++) {
        int j = lane + 32 * k, i1 = ir[k];
        bool win = (pickS[i1] == j);
        colsolS[j] = win ? i1 : -1;
        if (win) rowsolS[i1] = j;
    }
    __syncwarp();

    // ================= Phase B: reduction transfer =================
    for (int i = 0; i < NQ; i++) {
        if (cntS[i] == 1) {
            int j1 = rowsolS[i];
            float m = 3e38f;
#pragma unroll
            for (int k = 0; k < 4; k++) {
                int j = lane + 32 * k;
                float rc = costS[i * NQ + j] - vS[j];
                if (j != j1 && rc < m) m = rc;
            }
            unsigned em = __reduce_min_sync(FULLM, ford(m));
            if (lane == 0) vS[j1] = vS[j1] - funord(em);
            __syncwarp();
        }
    }

    // ================= Phase C: free-row list + v into registers ==========
    float v[4];
#pragma unroll
    for (int k = 0; k < 4; k++) v[k] = vS[lane + 32 * k];

    int nfree = 0;
#pragma unroll
    for (int k = 0; k < 4; k++) {
        bool f = (cntS[lane + 32 * k] == 0);
        unsigned bal = __ballot_sync(FULLM, f);
        if (f) freeS[nfree + __popc(bal & ((1u << lane) - 1))] = lane + 32 * k;
        nfree += __popc(bal);
    }
    __syncwarp();

    // ================= Phase D: augmenting row reduction (2 passes) =========
    // v lives in registers; owning lane applies the warp-uniform update.
    for (int pass = 0; pass < 2; pass++) {
        int kq = 0, prv = nfree;
        nfree = 0;
        int guard = 0;
        while (kq < prv && guard < 8 * NQ) {
            guard++;
            int i = freeS[kq]; kq++;
            // per-lane two smallest reduced costs
            float v1 = 3e38f, v2 = 3e38f; int i1 = 0, i2 = 0;
#pragma unroll
            for (int k = 0; k < 4; k++) {
                int j = lane + 32 * k;
                float rc = costS[i * NQ + j] - v[k];
                if (rc < v1)      { v2 = v1; i2 = i1; v1 = rc; i1 = j; }
                else if (rc < v2) { v2 = rc; i2 = j; }
            }
            unsigned e1   = ford(v1);
            unsigned em   = __reduce_min_sync(FULLM, e1);
            float umin    = funord(em);
            unsigned j1   = __reduce_min_sync(FULLM, (e1 == em) ? (unsigned)i1 : 0x7fffffffu);
            float sv; int sj;
            if ((unsigned)i1 == j1) { sv = v2; sj = i2; } else { sv = v1; sj = i1; }
            unsigned e2   = ford(sv);
            unsigned em2  = __reduce_min_sync(FULLM, e2);
            float usub    = funord(em2);

            int jt, i0;
            if (umin < usub) {
                jt = (int)j1;
                i0 = colsolS[jt];
                // owning lane updates its register copy of v[jt]
                if ((jt & 31) == lane) v[jt >> 5] -= (usub - umin);
            } else {
                unsigned j2 = __reduce_min_sync(FULLM, (e2 == em2) ? (unsigned)sj : 0x7fffffffu);
                jt = (int)j1;
                i0 = colsolS[jt];
                if (i0 >= 0) {
                    jt = (int)j2;
                    i0 = colsolS[jt];
                }
            }
            if (i0 >= 0) {
                if (umin < usub) { kq--; if (lane == 0) freeS[kq] = i0; }
                else             { if (lane == 0) freeS[nfree] = i0; nfree++; }
            }
            if (lane == 0) { rowsolS[i] = jt; colsolS[jt] = i; }
            __syncwarp();
        }
        if (kq < prv) {   // guard tripped: carry unprocessed rows to augment phase
            if (lane == 0)
                for (int t = kq; t < prv; t++) freeS[nfree + (t - kq)] = freeS[t];
            nfree += prv - kq;
            __syncwarp();
            break;
        }
    }
    __syncwarp();

    // ================= Phase E: duals u, matching pS ======================
#pragma unroll
    for (int k = 0; k < 4; k++) {
        int j  = lane + 32 * k;
        int i1 = colsolS[j];
        pS[j + 1] = i1 + 1;      // 0 if unassigned
        if (i1 >= 0) uS[i1 + 1] = costS[i1 * NQ + j] - v[k];
    }
    __syncwarp();

    // ================= Phase F: shortest augmenting paths ===================
    // packed key per owned column: (j << 8) | pS[j]  (j<=129, p<=128)
    int pk[4];
#pragma unroll
    for (int k = 0; k < 4; k++)
        pk[k] = ((1 + lane + 32 * k) << 8) | pS[1 + lane + 32 * k];

    for (int fi = 0; fi < nfree; fi++) {
        int i = freeS[fi] + 1;   // 1-indexed row
        float minv[4], dstart[4];
        int   pcol[4];
        unsigned usedb = 0u;
#pragma unroll
        for (int k = 0; k < 4; k++) { dstart[k] = 0.f; pcol[k] = 0; }

        const float* rowi = costS + (i - 1) * NQ + lane;
#pragma unroll
        for (int k = 0; k < 4; k++) {
            minv[k] = rowi[32 * k] - v[k];
            wayS[lane + 32 * k] = 0;
        }
        float bv = 3e38f; int bk = 0x7fffffff;
#pragma unroll
        for (int k = 0; k < 4; k++)
            if (minv[k] < bv) { bv = minv[k]; bk = pk[k]; }
        unsigned e    = ford(bv);
        unsigned emin = __reduce_min_sync(FULLM, e);
        float delta   = funord(emin);
        unsigned kmin = __reduce_min_sync(FULLM, (e == emin) ? (unsigned)bk : 0x7fffffffu);
        int jmin = (int)(kmin >> 8);
        int pj   = (int)(kmin & 0xffu);
        float dsum = delta;
#pragma unroll
        for (int k = 0; k < 4; k++) minv[k] -= delta;

        while (pj != 0) {
            int j0 = jmin;
            int i0 = pj;
            float ui0 = uS[i0];
            int jm1 = j0 - 1;
            if ((jm1 & 31) == lane) {
                int k0 = jm1 >> 5;
                usedb |= 1u << k0;
                dstart[k0] = dsum;
                pcol[k0]   = i0;
            }
            const float* row0 = costS + (i0 - 1) * NQ + lane;
            bv = 3e38f; bk = 0x7fffffff;
#pragma unroll
            for (int k = 0; k < 4; k++) {
                bool used = (usedb >> k) & 1u;
                float cur = row0[32 * k] - ui0 - v[k];
                if (!used && cur < minv[k]) { minv[k] = cur; wayS[lane + 32 * k] = j0; }
                if (!used && minv[k] < bv) { bv = minv[k]; bk = pk[k]; }
            }
            e    = (bk == 0x7fffffff) ? 0xffffffffu : ford(bv);
            emin = __reduce_min_sync(FULLM, e);
            delta = funord(emin);
            kmin = __reduce_min_sync(FULLM, (e == emin) ? (unsigned)bk : 0x7fffffffu);
            jmin = (int)(kmin >> 8);
            pj   = (int)(kmin & 0xffu);
            dsum += delta;
#pragma unroll
            for (int k = 0; k < 4; k++)
                if (!((usedb >> k) & 1u)) minv[k] -= delta;
        }

        __syncwarp();
        if (lane == 0) {
            int j = jmin;
            while (true) {
                int j1 = wayS[j - 1];
                if (j1 == 0) { pS[j] = i; break; }
                pS[j] = pS[j1];
                j = j1;
            }
        }
#pragma unroll
        for (int k = 0; k < 4; k++) {
            if ((usedb >> k) & 1u) {
                float corr = dsum - dstart[k];
                uS[pcol[k]] += corr;
                v[k] -= corr;
            }
        }
        if (lane == 0) uS[i] = dsum;
        __syncwarp();
#pragma unroll
        for (int k = 0; k < 4; k++)
            pk[k] = ((1 + lane + 32 * k) << 8) | pS[1 + lane + 32 * k];
    }

    // ================= Epilogue: col + loss =================
    float simsum = 0.f;
#pragma unroll
    for (int k = 0; k < 4; k++) {
        int j = 1 + lane + 32 * k;
        int row = pS[j] - 1;
        simsum += -costS[row * NQ + (j - 1)];
        out[1 + b * NQ + row] = (float)(j - 1);
    }
#pragma unroll
    for (int o = 16; o > 0; o >>= 1)
        simsum += __shfl_xor_sync(FULLM, simsum, o);
    if (lane == 0)
        atomicAdd(out, (1.f - simsum * (1.f / NQ)) * (1.f / NB));
}

// ---------------------------------------------------------------------------
extern "C" void kernel_launch(void* const* d_in, const int* in_sizes, int n_in,
                              void* d_out, int out_size) {
    const float* r = (const float*)d_in[0];
    const float* e = (const float*)d_in[1];
    float* out = (float*)d_out;

    cudaFuncSetAttribute(lsa_kernel,
                         cudaFuncAttributeMaxDynamicSharedMemorySize,
                         NQ * NQ * (int)sizeof(float));

    normalize_kernel<<<(2 * NB * NQ) / 8, 256>>>(r, e, out);

    dim3 gg(2, 2, NB);
    cost_kernel<<<gg, dim3(16, 16)>>>();

    lsa_kernel<<<NB, 256, NQ * NQ * (int)sizeof(float)>>>(out);
}

// round 13
// speedup vs baseline: 1.1514x; 1.1514x over previous
#include <cuda_runtime.h>
#include <math.h>

#define NB 64
#define NQ 128
#define ND 512
#define NP 129
#define EPS_ 1e-8f
#define FULLM 0xffffffffu
#define ARR_PASSES 3

// scratch (device globals; no allocation allowed)
__device__ float g_rn[NB * NQ * ND];
__device__ float g_en[NB * NQ * ND];
__device__ float g_cost[NB * NQ * NQ];

// order-preserving float <-> uint encoding (min uint == min float, exact)
__device__ __forceinline__ unsigned ford(float f) {
    unsigned u = __float_as_uint(f);
    return (u & 0x80000000u) ? ~u : (u | 0x80000000u);
}
__device__ __forceinline__ float funord(unsigned u) {
    return __uint_as_float((u & 0x80000000u) ? (u ^ 0x80000000u) : ~u);
}

#define FMA2(d, a, b) \
    asm("fma.rn.f32x2 %0, %1, %2, %3;" : "=l"(d) : "l"(a), "l"(b), "l"(d))
#define PACK2(d, x) \
    asm("mov.b64 %0, {%1, %1};" : "=l"(d) : "r"(__float_as_uint(x)))

// ---------------------------------------------------------------------------
// Kernel 1: row-wise normalize; also zeroes the loss accumulator.
// ---------------------------------------------------------------------------
__global__ void normalize_kernel(const float* __restrict__ r,
                                 const float* __restrict__ e,
                                 float* __restrict__ out) {
    if (blockIdx.x == 0 && threadIdx.x == 0) out[0] = 0.f;
    int gw = (blockIdx.x * blockDim.x + threadIdx.x) >> 5;
    int lane = threadIdx.x & 31;
    if (gw >= 2 * NB * NQ) return;
    const float* src;
    float* dst;
    if (gw < NB * NQ) { src = r + (size_t)gw * ND;            dst = g_rn + (size_t)gw * ND; }
    else              { src = e + (size_t)(gw - NB*NQ) * ND;  dst = g_en + (size_t)(gw - NB*NQ) * ND; }

    float vals[16];
    float ss = 0.f;
#pragma unroll
    for (int k = 0; k < 16; k++) {
        float x = src[lane + 32 * k] + EPS_;
        vals[k] = x;
        ss += x * x;
    }
#pragma unroll
    for (int o = 16; o > 0; o >>= 1)
        ss += __shfl_xor_sync(FULLM, ss, o);
    float n = sqrtf(ss);
    float s = 1.f / fmaxf(n, EPS_);
#pragma unroll
    for (int k = 0; k < 16; k++)
        dst[lane + 32 * k] = vals[k] * s;
}

// ---------------------------------------------------------------------------
// Kernel 2: batched cost GEMM with packed f32x2 FMA (R11-proven).
// ---------------------------------------------------------------------------
__global__ void cost_kernel() {
    __shared__ float sr[64][33];
    __shared__ __align__(16) float se2[32][130];   // [kk][col], 64 cols + pad
    int b  = blockIdx.z;
    int ti = blockIdx.y;
    int tj = blockIdx.x;
    const float* rb = g_rn + (size_t)b * NQ * ND + (size_t)ti * 64 * ND;
    const float* eb = g_en + (size_t)b * NQ * ND + (size_t)tj * 64 * ND;
    int tx = threadIdx.x, ty = threadIdx.y;
    int tid = ty * 16 + tx;

    unsigned long long acc[4][2];
#pragma unroll
    for (int u = 0; u < 4; u++) { acc[u][0] = 0ULL; acc[u][1] = 0ULL; }

    for (int k0 = 0; k0 < ND; k0 += 32) {
        for (int t = tid; t < 64 * 32; t += 256) {
            int row = t >> 5, kk = t & 31;
            sr[row][kk]  = rb[(size_t)row * ND + k0 + kk];
            se2[kk][row] = eb[(size_t)row * ND + k0 + kk];
        }
        __syncthreads();
#pragma unroll 8
        for (int kk = 0; kk < 32; kk++) {
            unsigned long long b01 = *(const unsigned long long*)&se2[kk][tx * 4];
            unsigned long long b23 = *(const unsigned long long*)&se2[kk][tx * 4 + 2];
#pragma unroll
            for (int u = 0; u < 4; u++) {
                unsigned long long a2;
                PACK2(a2, sr[ty * 4 + u][kk]);
                FMA2(acc[u][0], a2, b01);
                FMA2(acc[u][1], a2, b23);
            }
        }
        __syncthreads();
    }

    float* cb = g_cost + (size_t)b * NQ * NQ;
#pragma unroll
    for (int u = 0; u < 4; u++) {
        int i = ti * 64 + ty * 4 + u;
        float4 w;
        w.x = -__uint_as_float((unsigned)(acc[u][0]));
        w.y = -__uint_as_float((unsigned)(acc[u][0] >> 32));
        w.z = -__uint_as_float((unsigned)(acc[u][1]));
        w.w = -__uint_as_float((unsigned)(acc[u][1] >> 32));
        *(float4*)&cb[i * NQ + tj * 64 + tx * 4] = w;
    }
}

// ---------------------------------------------------------------------------
// Kernel 3: full JV (lapjv) LSA, one CTA per batch, warp 0 solves.
// (R11-proven body; only ARR pass count raised 2 -> 3.)
// ---------------------------------------------------------------------------
__global__ void lsa_kernel(float* __restrict__ out) {
    extern __shared__ float costS[];      // NQ*NQ floats
    __shared__ float vS[NQ];
    __shared__ float uS[NP];              // u indexed by row+1
    __shared__ int   pS[NP];              // col (1..NQ) -> row+1 ; 0 = free
    __shared__ int   wayS[NQ];
    __shared__ int   colsolS[NQ];
    __shared__ int   rowsolS[NQ];
    __shared__ int   cntS[NQ];
    __shared__ int   pickS[NQ];
    __shared__ int   freeS[NQ];

    int b   = blockIdx.x;
    int tid = threadIdx.x;

    const float4* cb = (const float4*)(g_cost + (size_t)b * NQ * NQ);
    float4* cs4 = (float4*)costS;
    for (int t = tid; t < NQ * NQ / 4; t += blockDim.x) cs4[t] = cb[t];
    if (tid < NQ) { cntS[tid] = 0; pickS[tid] = 0x7fffffff; }
    if (tid < NP) { uS[tid] = 0.f; pS[tid] = 0; }
    __syncthreads();
    if (tid >= 32) return;   // warp 0 only
    int lane = tid;

    // ================= Phase A: column reduction =================
    float vloc[4]; int ir[4];
#pragma unroll
    for (int k = 0; k < 4; k++) { vloc[k] = 3e38f; ir[k] = 0; }
    for (int i = 0; i < NQ; i++) {
#pragma unroll
        for (int k = 0; k < 4; k++) {
            float c = costS[i * NQ + lane + 32 * k];
            if (c < vloc[k]) { vloc[k] = c; ir[k] = i; }
        }
    }
#pragma unroll
    for (int k = 0; k < 4; k++) {
        vS[lane + 32 * k] = vloc[k];
        atomicMin(&pickS[ir[k]], lane + 32 * k);
        atomicAdd(&cntS[ir[k]], 1);
    }
    __syncwarp();
#pragma unroll
    for (int k = 0; k < 4; k++) {
        int j = lane + 32 * k, i1 = ir[k];
        bool win = (pickS[i1] == j);
        colsolS[j] = win ? i1 : -1;
        if (win) rowsolS[i1] = j;
    }
    __syncwarp();

    // ================= Phase B: reduction transfer =================
    for (int i = 0; i < NQ; i++) {
        if (cntS[i] == 1) {
            int j1 = rowsolS[i];
            float m = 3e38f;
#pragma unroll
            for (int k = 0; k < 4; k++) {
                int j = lane + 32 * k;
                float rc = costS[i * NQ + j] - vS[j];
                if (j != j1 && rc < m) m = rc;
            }
            unsigned em = __reduce_min_sync(FULLM, ford(m));
            if (lane == 0) vS[j1] = vS[j1] - funord(em);
            __syncwarp();
        }
    }

    // ================= Phase C: free-row list (ascending) =================
    int nfree = 0;
#pragma unroll
    for (int k = 0; k < 4; k++) {
        bool f = (cntS[lane + 32 * k] == 0);
        unsigned bal = __ballot_sync(FULLM, f);
        if (f) freeS[nfree + __popc(bal & ((1u << lane) - 1))] = lane + 32 * k;
        nfree += __popc(bal);
    }
    __syncwarp();

    // ================= Phase D: augmenting row reduction (3 passes) =========
    for (int pass = 0; pass < ARR_PASSES; pass++) {
        int kq = 0, prv = nfree;
        nfree = 0;
        int guard = 0;
        while (kq < prv && guard < 8 * NQ) {
            guard++;
            int i = freeS[kq]; kq++;
            __syncwarp();
            // per-lane two smallest reduced costs
            float v1 = 3e38f, v2 = 3e38f; int i1 = 0, i2 = 0;
#pragma unroll
            for (int k = 0; k < 4; k++) {
                int j = lane + 32 * k;
                float rc = costS[i * NQ + j] - vS[j];
                if (rc < v1)      { v2 = v1; i2 = i1; v1 = rc; i1 = j; }
                else if (rc < v2) { v2 = rc; i2 = j; }
            }
            unsigned e1   = ford(v1);
            unsigned em   = __reduce_min_sync(FULLM, e1);
            float umin    = funord(em);
            unsigned j1   = __reduce_min_sync(FULLM, (e1 == em) ? (unsigned)i1 : 0x7fffffffu);
            float sv; int sj;
            if ((unsigned)i1 == j1) { sv = v2; sj = i2; } else { sv = v1; sj = i1; }
            unsigned e2   = ford(sv);
            unsigned em2  = __reduce_min_sync(FULLM, e2);
            float usub    = funord(em2);
            unsigned j2   = __reduce_min_sync(FULLM, (e2 == em2) ? (unsigned)sj : 0x7fffffffu);

            int jt = (int)j1;
            int i0 = colsolS[jt];
            if (umin < usub) {
                if (lane == 0) vS[jt] -= (usub - umin);
            } else if (i0 >= 0) {
                jt = (int)j2;
                i0 = colsolS[jt];
            }
            if (i0 >= 0) {
                if (umin < usub) { kq--; if (lane == 0) freeS[kq] = i0; }
                else             { if (lane == 0) freeS[nfree] = i0; nfree++; }
            }
            if (lane == 0) { rowsolS[i] = jt; colsolS[jt] = i; }
            __syncwarp();
        }
        if (kq < prv) {   // guard tripped: carry unprocessed rows to augment phase
            if (lane == 0)
                for (int t = kq; t < prv; t++) freeS[nfree + (t - kq)] = freeS[t];
            nfree += prv - kq;
            __syncwarp();
            break;
        }
    }
    __syncwarp();

    // ================= Phase E: duals u, matching pS, v into registers ======
#pragma unroll
    for (int k = 0; k < 4; k++) {
        int j  = lane + 32 * k;
        int i1 = colsolS[j];
        pS[j + 1] = i1 + 1;      // 0 if unassigned
        if (i1 >= 0) uS[i1 + 1] = costS[i1 * NQ + j] - vS[j];
    }
    float v[4];
#pragma unroll
    for (int k = 0; k < 4; k++) v[k] = vS[lane + 32 * k];
    __syncwarp();

    // ================= Phase F: shortest augmenting paths ===================
    // packed key per owned column: (j << 8) | pS[j]  (j<=129, p<=128)
    int pk[4];
#pragma unroll
    for (int k = 0; k < 4; k++)
        pk[k] = ((1 + lane + 32 * k) << 8) | pS[1 + lane + 32 * k];

    for (int fi = 0; fi < nfree; fi++) {
        int i = freeS[fi] + 1;   // 1-indexed row
        float minv[4], dstart[4];
        int   pcol[4];
        unsigned usedb = 0u;
#pragma unroll
        for (int k = 0; k < 4; k++) { dstart[k] = 0.f; pcol[k] = 0; }

        const float* rowi = costS + (i - 1) * NQ + lane;
#pragma unroll
        for (int k = 0; k < 4; k++) {
            minv[k] = rowi[32 * k] - v[k];
            wayS[lane + 32 * k] = 0;
        }
        float bv = 3e38f; int bk = 0x7fffffff;
#pragma unroll
        for (int k = 0; k < 4; k++)
            if (minv[k] < bv) { bv = minv[k]; bk = pk[k]; }
        unsigned e    = ford(bv);
        unsigned emin = __reduce_min_sync(FULLM, e);
        float delta   = funord(emin);
        unsigned kmin = __reduce_min_sync(FULLM, (e == emin) ? (unsigned)bk : 0x7fffffffu);
        int jmin = (int)(kmin >> 8);
        int pj   = (int)(kmin & 0xffu);
        float dsum = delta;
#pragma unroll
        for (int k = 0; k < 4; k++) minv[k] -= delta;

        while (pj != 0) {
            int j0 = jmin;
            int i0 = pj;
            float ui0 = uS[i0];
            int jm1 = j0 - 1;
            if ((jm1 & 31) == lane) {
                int k0 = jm1 >> 5;
                usedb |= 1u << k0;
                dstart[k0] = dsum;
                pcol[k0]   = i0;
            }
            const float* row0 = costS + (i0 - 1) * NQ + lane;
            bv = 3e38f; bk = 0x7fffffff;
#pragma unroll
            for (int k = 0; k < 4; k++) {
                bool used = (usedb >> k) & 1u;
                float cur = row0[32 * k] - ui0 - v[k];
                if (!used && cur < minv[k]) { minv[k] = cur; wayS[lane + 32 * k] = j0; }
                if (!used && minv[k] < bv) { bv = minv[k]; bk = pk[k]; }
            }
            e    = (bk == 0x7fffffff) ? 0xffffffffu : ford(bv);
            emin = __reduce_min_sync(FULLM, e);
            delta = funord(emin);
            kmin = __reduce_min_sync(FULLM, (e == emin) ? (unsigned)bk : 0x7fffffffu);
            jmin = (int)(kmin >> 8);
            pj   = (int)(kmin & 0xffu);
            dsum += delta;
#pragma unroll
            for (int k = 0; k < 4; k++)
                if (!((usedb >> k) & 1u)) minv[k] -= delta;
        }

        __syncwarp();
        if (lane == 0) {
            int j = jmin;
            while (true) {
                int j1 = wayS[j - 1];
                if (j1 == 0) { pS[j] = i; break; }
                pS[j] = pS[j1];
                j = j1;
            }
        }
#pragma unroll
        for (int k = 0; k < 4; k++) {
            if ((usedb >> k) & 1u) {
                float corr = dsum - dstart[k];
                uS[pcol[k]] += corr;
                v[k] -= corr;
            }
        }
        if (lane == 0) uS[i] = dsum;
        __syncwarp();
#pragma unroll
        for (int k = 0; k < 4; k++)
            pk[k] = ((1 + lane + 32 * k) << 8) | pS[1 + lane + 32 * k];
    }

    // ================= Epilogue: col + loss =================
    float simsum = 0.f;
#pragma unroll
    for (int k = 0; k < 4; k++) {
        int j = 1 + lane + 32 * k;
        int row = pS[j] - 1;
        simsum += -costS[row * NQ + (j - 1)];
        out[1 + b * NQ + row] = (float)(j - 1);
    }
#pragma unroll
    for (int o = 16; o > 0; o >>= 1)
        simsum += __shfl_xor_sync(FULLM, simsum, o);
    if (lane == 0)
        atomicAdd(out, (1.f - simsum * (1.f / NQ)) * (1.f / NB));
}

// ---------------------------------------------------------------------------
extern "C" void kernel_launch(void* const* d_in, const int* in_sizes, int n_in,
                              void* d_out, int out_size) {
    const float* r = (const float*)d_in[0];
    const float* e = (const float*)d_in[1];
    float* out = (float*)d_out;

    cudaFuncSetAttribute(lsa_kernel,
                         cudaFuncAttributeMaxDynamicSharedMemorySize,
                         NQ * NQ * (int)sizeof(float));

    normalize_kernel<<<(2 * NB * NQ) / 8, 256>>>(r, e, out);

    dim3 gg(2, 2, NB);
    cost_kernel<<<gg, dim3(16, 16)>>>();

    lsa_kernel<<<NB, 256, NQ * NQ * (int)sizeof(float)>>>(out);
}